// round 4
// baseline (speedup 1.0000x reference)
#include <cuda_runtime.h>
#include <cstdint>

#define ROWS        8192
#define COLS        32768
#define K_TOP       32
#define PRE_THRESH  2.0f

#define SEGS_PER_ROW 4
#define SEG          (COLS / SEGS_PER_ROW)
#define STH          512
#define SEG_ITERS    (SEG / 4 / STH)
#define SEG_CAP      512
#define CAND_CAP     1536
#define SMALL_CAP    256

// Global scratch (zero-init at load; reset by the selecting block each run)
__device__ unsigned long long g_cand[(size_t)ROWS * CAND_CAP];
__device__ int                g_cnt[ROWS];
__device__ int                g_arrive[ROWS];

__device__ __forceinline__ unsigned fmap(float f) {
    unsigned b = __float_as_uint(f);
    return (b & 0x80000000u) ? ~b : (b | 0x80000000u);
}
__device__ __forceinline__ float unfmap(unsigned u) {
    unsigned b = (u & 0x80000000u) ? (u ^ 0x80000000u) : ~u;
    return __uint_as_float(b);
}
// unique key: value desc, index asc tiebreak (matches jax.lax.top_k)
__device__ __forceinline__ unsigned long long make_key(float v, int idx) {
    return ((unsigned long long)fmap(v) << 32) | (unsigned)(~idx);
}

// warp-aggregated histogram add (collapses same-digit atomics to 1/warp)
__device__ __forceinline__ void hist_add(int* hist, int digit) {
    const unsigned act   = __activemask();
    const unsigned peers = __match_any_sync(act, digit);
    const int      lane  = threadIdx.x & 31;
    if ((__ffs(peers) - 1) == lane)
        atomicAdd(&hist[digit], __popc(peers));
}

__global__ __launch_bounds__(STH) void topk_fused_kernel(
    const float* __restrict__ x, float* __restrict__ out)
{
    __shared__ unsigned long long s_cand[CAND_CAP];  // stream uses first SEG_CAP
    __shared__ int s_cnt, s_base, s_last;
    __shared__ int s_hist[256];
    __shared__ int s_wtot[8];
    __shared__ int s_digit, s_want, s_bcnt, s_scnt;
    __shared__ unsigned long long s_small[SMALL_CAP];
    __shared__ unsigned long long s_T;

    const int seg_id = blockIdx.x;
    const int row = seg_id >> 2;
    const int seg = seg_id & 3;
    const size_t row_off = (size_t)row * COLS;
    const size_t base = row_off + (size_t)seg * SEG;
    const int tid  = threadIdx.x;
    const int lane = tid & 31;
    const int warp = tid >> 5;

    if (tid == 0) s_cnt = 0;
    __syncthreads();

    // ---------------- Phase 1: stream read + zero + candidate gather -------
    const float4* __restrict__ xin = reinterpret_cast<const float4*>(x + base);
    float4* __restrict__       zo  = reinterpret_cast<float4*>(out + base);
    const float4 z4 = make_float4(0.f, 0.f, 0.f, 0.f);

    #pragma unroll
    for (int k = 0; k < SEG_ITERS; k++) {
        const int j = tid + k * STH;
        float4 v = __ldcs(&xin[j]);
        __stcs(&zo[j], z4);
        const int gidx = seg * SEG + j * 4;
        if (v.x >= PRE_THRESH) { int p = atomicAdd(&s_cnt, 1); if (p < SEG_CAP) s_cand[p] = make_key(v.x, gidx + 0); }
        if (v.y >= PRE_THRESH) { int p = atomicAdd(&s_cnt, 1); if (p < SEG_CAP) s_cand[p] = make_key(v.y, gidx + 1); }
        if (v.z >= PRE_THRESH) { int p = atomicAdd(&s_cnt, 1); if (p < SEG_CAP) s_cand[p] = make_key(v.z, gidx + 2); }
        if (v.w >= PRE_THRESH) { int p = atomicAdd(&s_cnt, 1); if (p < SEG_CAP) s_cand[p] = make_key(v.w, gidx + 3); }
    }
    __syncthreads();

    const int segcnt = s_cnt;
    if (tid == 0) {
        int add = (segcnt > SEG_CAP) ? (CAND_CAP + 1 + segcnt) : segcnt;
        s_base = atomicAdd(&g_cnt[row], add);
    }
    __syncthreads();

    {
        const int wcnt = min(segcnt, SEG_CAP);
        const int b = s_base;
        for (int j = tid; j < wcnt; j += STH) {
            const int pos = b + j;
            if (pos < CAND_CAP)
                g_cand[(size_t)row * CAND_CAP + pos] = s_cand[j];
        }
    }

    // -------- Arrival: last segment block of the row performs the select ---
    __syncthreads();
    if (tid == 0) {
        __threadfence();                         // release: cand + zero stores
        s_last = (atomicAdd(&g_arrive[row], 1) == SEGS_PER_ROW - 1);
    }
    __syncthreads();
    if (!s_last) return;
    __threadfence();                             // acquire: peers' stores

    // ---------------- Phase 2: exact top-K select for this row -------------
    const int cnt = g_cnt[row];
    const bool fast = (cnt >= K_TOP) && (cnt <= CAND_CAP);
    const int n = fast ? cnt : COLS;

    if (fast) {
        for (int j = tid; j < cnt; j += STH)
            s_cand[j] = g_cand[(size_t)row * CAND_CAP + j];
    }
    __syncthreads();

    unsigned long long prefix = 0, T = 0;
    int want = K_TOP;

    for (int shift = 56; shift >= 0; shift -= 8) {
        if (tid < 256) s_hist[tid] = 0;
        if (tid == 0) s_scnt = 0;
        __syncthreads();

        for (int j = tid; j < n; j += STH) {
            unsigned long long key = fast ? s_cand[j] : make_key(x[row_off + j], j);
            if (shift == 56 || (key >> (shift + 8)) == prefix)
                hist_add(s_hist, (int)((key >> shift) & 255));
        }
        __syncthreads();

        // inclusive suffix-sum over 256 bins (first 8 warps)
        int h = 0, v = 0;
        if (tid < 256) {
            h = s_hist[tid]; v = h;
            #pragma unroll
            for (int off = 1; off < 32; off <<= 1) {
                int o = __shfl_down_sync(0xffffffffu, v, off);
                if (lane + off < 32) v += o;
            }
            if (lane == 0) s_wtot[warp] = v;
        }
        __syncthreads();
        if (tid < 256) {
            int add = 0;
            #pragma unroll
            for (int w2 = 0; w2 < 8; w2++)
                if (w2 > warp) add += s_wtot[w2];
            const int suf  = v + add;
            const int suf1 = suf - h;
            if (suf >= want && suf1 < want) {
                s_digit = tid;
                s_want  = want - suf1;
                s_bcnt  = h;
            }
        }
        __syncthreads();

        prefix = (prefix << 8) | (unsigned long long)s_digit;
        want   = s_want;
        const int c = s_bcnt;

        if (want == c) {                 // whole boundary bin selected
            T = prefix << shift;
            break;
        }
        if (c <= SMALL_CAP) {            // compact boundary keys, rank-select
            for (int j = tid; j < n; j += STH) {
                unsigned long long key = fast ? s_cand[j] : make_key(x[row_off + j], j);
                if ((key >> shift) == prefix) {
                    int p = atomicAdd(&s_scnt, 1);
                    s_small[p] = key;
                }
            }
            __syncthreads();
            if (tid < c) {
                const unsigned long long mykey = s_small[tid];
                int rank = 0;
                for (int j = 0; j < c; j++)
                    rank += (s_small[j] > mykey);
                if (rank == want - 1) s_T = mykey;  // unique keys -> exactly one
            }
            __syncthreads();
            T = s_T;
            break;
        }
        __syncthreads();
        // terminates: at shift==0 keys within a bin are identical -> unique -> c==1==want
    }

    // ---------------- Phase 3: scatter winners over the zeroed row ---------
    for (int j = tid; j < n; j += STH) {
        unsigned long long key = fast ? s_cand[j] : make_key(x[row_off + j], j);
        if (key >= T) {
            const int idx = (int)(~(unsigned)key) & (COLS - 1);
            const float v = unfmap((unsigned)(key >> 32));
            out[row_off + idx] = fmaxf(v, 0.f);
        }
    }

    // Reset counters for deterministic graph replays.
    __syncthreads();
    if (tid == 0) {
        g_cnt[row] = 0;
        g_arrive[row] = 0;
    }
}

extern "C" void kernel_launch(void* const* d_in, const int* in_sizes, int n_in,
                              void* d_out, int out_size)
{
    const float* x = (const float*)d_in[0];
    float* out = (float*)d_out;
    topk_fused_kernel<<<ROWS * SEGS_PER_ROW, STH>>>(x, out);
}

// round 5
// speedup vs baseline: 1.3012x; 1.3012x over previous
#include <cuda_runtime.h>
#include <cstdint>

#define ROWS        8192
#define COLS        32768
#define K_TOP       32
#define PRE_THRESH  2.8f

#define SEGS_PER_ROW 4
#define SEG          (COLS / SEGS_PER_ROW)
#define STH          512
#define SEG_ITERS    (SEG / 4 / STH)      // 4
#define SEG_CAP      128                   // per-segment cap (mean ~21, sigma ~4.6)
#define CAND_CAP     512                   // per-row cap (mean ~84, sigma ~9.1)
#define QTH          256

// Global scratch (zero-init at load; select kernel resets counters)
__device__ unsigned long long g_cand[(size_t)ROWS * CAND_CAP];
__device__ int                g_cnt[ROWS];

__device__ __forceinline__ unsigned fmap(float f) {
    unsigned b = __float_as_uint(f);
    return (b & 0x80000000u) ? ~b : (b | 0x80000000u);
}
__device__ __forceinline__ float unfmap(unsigned u) {
    unsigned b = (u & 0x80000000u) ? (u ^ 0x80000000u) : ~u;
    return __uint_as_float(b);
}
// unique key: value desc, index asc tiebreak (matches jax.lax.top_k)
__device__ __forceinline__ unsigned long long make_key(float v, int idx) {
    return ((unsigned long long)fmap(v) << 32) | (unsigned)(~idx);
}

// warp-aggregated histogram add (fallback path only)
__device__ __forceinline__ void hist_add(int* hist, int digit) {
    const unsigned act   = __activemask();
    const unsigned peers = __match_any_sync(act, digit);
    const int      lane  = threadIdx.x & 31;
    if ((__ffs(peers) - 1) == lane)
        atomicAdd(&hist[digit], __popc(peers));
}

// ---------------------------------------------------------------------------
// Kernel 1: pure streaming pass. Front-batched loads (MLP=4), zero-fill,
// rare candidate gather at 2.8-sigma threshold.
// ---------------------------------------------------------------------------
__global__ __launch_bounds__(STH) void stream_kernel(
    const float* __restrict__ x, float* __restrict__ out)
{
    __shared__ int s_cnt;
    __shared__ int s_base;
    __shared__ unsigned long long s_cand[SEG_CAP];

    const int seg_id = blockIdx.x;
    const int row = seg_id >> 2;
    const int seg = seg_id & 3;
    const size_t base = (size_t)row * COLS + (size_t)seg * SEG;
    const int tid = threadIdx.x;

    if (tid == 0) s_cnt = 0;
    __syncthreads();

    const float4* __restrict__ xin = reinterpret_cast<const float4*>(x + base);
    float4* __restrict__       zo  = reinterpret_cast<float4*>(out + base);
    const float4 z4 = make_float4(0.f, 0.f, 0.f, 0.f);

    // front-batched independent loads
    float4 v[SEG_ITERS];
    #pragma unroll
    for (int k = 0; k < SEG_ITERS; k++)
        v[k] = __ldcs(&xin[tid + k * STH]);
    #pragma unroll
    for (int k = 0; k < SEG_ITERS; k++)
        __stcs(&zo[tid + k * STH], z4);

    #pragma unroll
    for (int k = 0; k < SEG_ITERS; k++) {
        const int gidx = seg * SEG + (tid + k * STH) * 4;
        if (v[k].x >= PRE_THRESH) { int p = atomicAdd(&s_cnt, 1); if (p < SEG_CAP) s_cand[p] = make_key(v[k].x, gidx + 0); }
        if (v[k].y >= PRE_THRESH) { int p = atomicAdd(&s_cnt, 1); if (p < SEG_CAP) s_cand[p] = make_key(v[k].y, gidx + 1); }
        if (v[k].z >= PRE_THRESH) { int p = atomicAdd(&s_cnt, 1); if (p < SEG_CAP) s_cand[p] = make_key(v[k].z, gidx + 2); }
        if (v[k].w >= PRE_THRESH) { int p = atomicAdd(&s_cnt, 1); if (p < SEG_CAP) s_cand[p] = make_key(v[k].w, gidx + 3); }
    }
    __syncthreads();

    const int cnt = s_cnt;
    if (tid == 0) {
        // poison the row count on segment overflow -> kernel 2 falls back
        int add = (cnt > SEG_CAP) ? (CAND_CAP + 1 + cnt) : cnt;
        s_base = atomicAdd(&g_cnt[row], add);
    }
    __syncthreads();

    const int wcnt = min(cnt, SEG_CAP);
    const int b = s_base;
    for (int j = tid; j < wcnt; j += STH) {
        const int pos = b + j;
        if (pos < CAND_CAP)
            g_cand[(size_t)row * CAND_CAP + pos] = s_cand[j];
    }
}

// ---------------------------------------------------------------------------
// Kernel 2: exact top-K by O(c^2) rank-select over unique 64-bit keys.
// Fallback: full-row radix select (correct for arbitrary input).
// ---------------------------------------------------------------------------
__global__ __launch_bounds__(QTH) void select_kernel(
    const float* __restrict__ x, float* __restrict__ out)
{
    __shared__ unsigned long long s_cand[CAND_CAP];
    __shared__ int s_hist[256];
    __shared__ int s_wtot[8];
    __shared__ int s_digit, s_want, s_bcnt, s_scnt;
    __shared__ unsigned long long s_small[256];
    __shared__ unsigned long long s_T;

    const int row = blockIdx.x;
    const size_t row_off = (size_t)row * COLS;
    const int tid  = threadIdx.x;
    const int lane = tid & 31;
    const int warp = tid >> 5;

    const int cnt = g_cnt[row];
    const bool fast = (cnt >= K_TOP) && (cnt <= CAND_CAP);

    if (fast) {
        // ---------------- fast path: rank-select over c<=512 unique keys ---
        for (int j = tid; j < cnt; j += QTH)
            s_cand[j] = g_cand[(size_t)row * CAND_CAP + j];
        __syncthreads();

        #pragma unroll
        for (int t = tid; t < CAND_CAP; t += QTH) {
            if (t < cnt) {
                const unsigned long long mykey = s_cand[t];
                int rank = 0;
                for (int j = 0; j < cnt; j++)
                    rank += (s_cand[j] > mykey);
                if (rank < K_TOP) {
                    const int idx = (int)(~(unsigned)mykey) & (COLS - 1);
                    const float v = unfmap((unsigned)(mykey >> 32));
                    out[row_off + idx] = fmaxf(v, 0.f);
                }
            }
        }
    } else {
        // ---------------- fallback: full-row radix select ------------------
        const int n = COLS;
        unsigned long long prefix = 0, T = 0;
        int want = K_TOP;

        for (int shift = 56; shift >= 0; shift -= 8) {
            s_hist[tid] = 0;
            if (tid == 0) s_scnt = 0;
            __syncthreads();
            for (int j = tid; j < n; j += QTH) {
                unsigned long long key = make_key(x[row_off + j], j);
                if (shift == 56 || (key >> (shift + 8)) == prefix)
                    hist_add(s_hist, (int)((key >> shift) & 255));
            }
            __syncthreads();

            // inclusive suffix-sum over 256 bins
            const int h = s_hist[tid];
            int v = h;
            #pragma unroll
            for (int off = 1; off < 32; off <<= 1) {
                int o = __shfl_down_sync(0xffffffffu, v, off);
                if (lane + off < 32) v += o;
            }
            if (lane == 0) s_wtot[warp] = v;
            __syncthreads();
            int add = 0;
            #pragma unroll
            for (int w2 = 0; w2 < 8; w2++)
                if (w2 > warp) add += s_wtot[w2];
            const int suf  = v + add;
            const int suf1 = suf - h;
            if (suf >= want && suf1 < want) {
                s_digit = tid;
                s_want  = want - suf1;
                s_bcnt  = h;
            }
            __syncthreads();

            prefix = (prefix << 8) | (unsigned long long)s_digit;
            want   = s_want;
            const int c = s_bcnt;

            if (want == c) { T = prefix << shift; break; }
            if (c <= 256) {
                for (int j = tid; j < n; j += QTH) {
                    unsigned long long key = make_key(x[row_off + j], j);
                    if ((key >> shift) == prefix) {
                        int p = atomicAdd(&s_scnt, 1);
                        s_small[p] = key;
                    }
                }
                __syncthreads();
                if (tid < c) {
                    const unsigned long long mykey = s_small[tid];
                    int rank = 0;
                    for (int j = 0; j < c; j++)
                        rank += (s_small[j] > mykey);
                    if (rank == want - 1) s_T = mykey;
                }
                __syncthreads();
                T = s_T;
                break;
            }
            __syncthreads();
        }

        for (int j = tid; j < n; j += QTH) {
            unsigned long long key = make_key(x[row_off + j], j);
            if (key >= T) {
                const int idx = (int)(~(unsigned)key) & (COLS - 1);
                const float v = unfmap((unsigned)(key >> 32));
                out[row_off + idx] = fmaxf(v, 0.f);
            }
        }
    }

    // Reset counter for deterministic graph replays.
    __syncthreads();
    if (tid == 0) g_cnt[row] = 0;
}

extern "C" void kernel_launch(void* const* d_in, const int* in_sizes, int n_in,
                              void* d_out, int out_size)
{
    const float* x = (const float*)d_in[0];
    float* out = (float*)d_out;
    stream_kernel<<<ROWS * SEGS_PER_ROW, STH>>>(x, out);
    select_kernel<<<ROWS, QTH>>>(x, out);
}